// round 3
// baseline (speedup 1.0000x reference)
#include <cuda_runtime.h>
#include <math.h>

#define BN   32768
#define DD   768
#define HD   256
#define H2   128
#define EE   8
#define LNEPS 1e-5f

// d_out layout: final[B], fraction[E], prob[E], logits[B*E]
#define OFF_FINAL 0
#define OFF_FRAC  (BN)
#define OFF_PROB  (BN + EE)
#define OFF_LOG   (BN + 2*EE)

// ---------------- device scratch (no allocations) ----------------
__device__ float g_xhat[(size_t)BN*DD];
__device__ float g_W1f[EE*DD*HD];
__device__ float g_c1f[EE*HD];
__device__ float g_W2f[EE*HD*H2];
__device__ float g_c2f[EE*H2];
__device__ float g_W3f[EE*H2];
__device__ float g_c3f[EE];
__device__ float g_Wrf[EE*DD];
__device__ float g_brf[EE];
__device__ int   g_cnt[EE];
__device__ int   g_list[(size_t)EE*BN];
__device__ int2  g_topi[BN];
__device__ float2 g_topw[BN];
__device__ float g_outs[(size_t)EE*BN];
__device__ float g_part[64*EE];

// ---------------- helpers ----------------
__device__ __forceinline__ float warpSum(float v){
#pragma unroll
  for (int o=16;o>0;o>>=1) v += __shfl_xor_sync(0xffffffffu, v, o);
  return v;
}

__device__ float blockSumTo0(float v){
  __shared__ float red[32];
  int lane = threadIdx.x & 31, w = threadIdx.x >> 5;
  v = warpSum(v);
  __syncthreads();
  if (lane==0) red[w]=v;
  __syncthreads();
  float t = 0.f;
  if (threadIdx.x==0){
    int nw = blockDim.x >> 5;
    for (int i=0;i<nw;i++) t += red[i];
  }
  return t;
}

__device__ __forceinline__ float gelu_exact(float x){ return x*normcdff(x); }

// packed f32x2 FMA: 2 FMAs per instruction on Blackwell
__device__ __forceinline__ void ffma2(float2& d, const float2 a, const float2 b){
  unsigned long long& dd = *reinterpret_cast<unsigned long long*>(&d);
  unsigned long long aa;
  unsigned long long bb;
  memcpy(&aa,&a,8); memcpy(&bb,&b,8);
  asm("fma.rn.f32x2 %0, %1, %2, %0;" : "+l"(dd) : "l"(aa), "l"(bb));
}

// ---------------- zero counters ----------------
__global__ void k_zero(){
  if (threadIdx.x < EE) g_cnt[threadIdx.x] = 0;
}

// ---------------- weight folding ----------------
__global__ void k_fold_router(const float* __restrict__ gr, const float* __restrict__ brln,
                              const float* __restrict__ Wr, const float* __restrict__ br){
  int e = blockIdx.x, t = threadIdx.x;
  float s = 0.f;
  for (int d=t; d<DD; d+=256){
    float w = Wr[e*DD+d];
    g_Wrf[e*DD+d] = gr[d]*w;
    s += brln[d]*w;
  }
  s = blockSumTo0(s);
  if (t==0) g_brf[e] = br[e] + s;
}

__global__ void k_fold_w1(const float* __restrict__ ln1g, const float* __restrict__ W1){
  int i = blockIdx.x*256 + threadIdx.x;
  int e = i/(DD*HD); int d = (i/HD)%DD;
  g_W1f[i] = ln1g[e*DD+d]*W1[i];
}

__global__ void k_fold_c1(const float* __restrict__ ln1b, const float* __restrict__ W1,
                          const float* __restrict__ b1){
  int h = blockIdx.x, e = blockIdx.y, t = threadIdx.x;
  float s = 0.f;
  for (int d=t; d<DD; d+=256) s += ln1b[e*DD+d]*W1[((size_t)e*DD+d)*HD + h];
  s = blockSumTo0(s);
  if (t==0) g_c1f[e*HD+h] = b1[e*HD+h] + s;
}

__global__ void k_fold_w2(const float* __restrict__ ln2g, const float* __restrict__ W2){
  int i = blockIdx.x*256 + threadIdx.x;
  int e = i/(HD*H2); int h = (i/H2)%HD;
  g_W2f[i] = ln2g[e*HD+h]*W2[i];
}

__global__ void k_fold_c2(const float* __restrict__ ln2b, const float* __restrict__ W2,
                          const float* __restrict__ b2){
  int hh = blockIdx.x, e = blockIdx.y, t = threadIdx.x;
  float s = 0.f;
  for (int h=t; h<HD; h+=256) s += ln2b[e*HD+h]*W2[((size_t)e*HD+h)*H2 + hh];
  s = blockSumTo0(s);
  if (t==0) g_c2f[e*H2+hh] = b2[e*H2+hh] + s;
}

__global__ void k_fold_l3(const float* __restrict__ ln3g, const float* __restrict__ ln3b,
                          const float* __restrict__ W3, const float* __restrict__ b3){
  int e = blockIdx.x, t = threadIdx.x; // 128 threads
  float w = W3[e*H2+t];
  g_W3f[e*H2+t] = ln3g[e*H2+t]*w;
  float s = blockSumTo0(ln3b[e*H2+t]*w);
  if (t==0) g_c3f[e] = b3[e] + s;
}

// ---------------- rows: input LN -> xhat, router, top-2, lists ----------------
__global__ void __launch_bounds__(256)
k_rows(const float* __restrict__ x, const float* __restrict__ gin,
       const float* __restrict__ bin, float* __restrict__ logits_out){
  int lane = threadIdx.x & 31;
  int wid  = threadIdx.x >> 5;
  int row  = (blockIdx.x<<3) + wid;
  const float* xr = x + (size_t)row*DD;
  const int d0 = lane*24;

  float v[24];
  float s=0.f, s2=0.f;
#pragma unroll
  for (int q=0;q<6;q++){
    float4 t4 = *(const float4*)(xr + d0 + 4*q);
    v[4*q+0]=t4.x; v[4*q+1]=t4.y; v[4*q+2]=t4.z; v[4*q+3]=t4.w;
  }
#pragma unroll
  for (int j=0;j<24;j++){ s+=v[j]; s2+=v[j]*v[j]; }
  s = warpSum(s); s2 = warpSum(s2);
  float mu = s*(1.f/768.f);
  float rstd = rsqrtf(fmaxf(s2*(1.f/768.f)-mu*mu,0.f)+LNEPS);

  s=0.f; s2=0.f;
#pragma unroll
  for (int q=0;q<6;q++){
    float4 g4 = *(const float4*)(gin + d0 + 4*q);
    float4 b4 = *(const float4*)(bin + d0 + 4*q);
    v[4*q+0] = (v[4*q+0]-mu)*rstd*g4.x + b4.x;
    v[4*q+1] = (v[4*q+1]-mu)*rstd*g4.y + b4.y;
    v[4*q+2] = (v[4*q+2]-mu)*rstd*g4.z + b4.z;
    v[4*q+3] = (v[4*q+3]-mu)*rstd*g4.w + b4.w;
  }
#pragma unroll
  for (int j=0;j<24;j++){ s+=v[j]; s2+=v[j]*v[j]; }
  s = warpSum(s); s2 = warpSum(s2);
  float mu2 = s*(1.f/768.f);
  float rstd2 = rsqrtf(fmaxf(s2*(1.f/768.f)-mu2*mu2,0.f)+LNEPS);

  float* xo = g_xhat + (size_t)row*DD + d0;
#pragma unroll
  for (int q=0;q<6;q++){
    float4 t4;
    t4.x = (v[4*q+0]-mu2)*rstd2; t4.y = (v[4*q+1]-mu2)*rstd2;
    t4.z = (v[4*q+2]-mu2)*rstd2; t4.w = (v[4*q+3]-mu2)*rstd2;
    v[4*q+0]=t4.x; v[4*q+1]=t4.y; v[4*q+2]=t4.z; v[4*q+3]=t4.w;
    *(float4*)(xo + 4*q) = t4;
  }

  // router logits (router LN folded into Wrf/brf)
  float acc[8];
#pragma unroll
  for (int e=0;e<8;e++){
    const float* wr = g_Wrf + e*DD + d0;
    float a = 0.f;
#pragma unroll
    for (int q=0;q<6;q++){
      float4 w4 = *(const float4*)(wr + 4*q);
      a += v[4*q+0]*w4.x + v[4*q+1]*w4.y + v[4*q+2]*w4.z + v[4*q+3]*w4.w;
    }
    acc[e] = warpSum(a);
  }

  if (lane==0){
    float lg[8];
#pragma unroll
    for (int e=0;e<8;e++) lg[e] = acc[e] + g_brf[e];
    float* lo = logits_out + (size_t)row*8;
#pragma unroll
    for (int e=0;e<8;e++) lo[e] = lg[e];
    int i0=0; float v0=lg[0];
#pragma unroll
    for (int e=1;e<8;e++) if (lg[e]>v0){v0=lg[e]; i0=e;}
    int i1=-1; float v1=-3.4e38f;
#pragma unroll
    for (int e=0;e<8;e++) if (e!=i0 && lg[e]>v1){v1=lg[e]; i1=e;}
    float ee = expf(v1-v0);
    float w0 = 1.f/(1.f+ee);
    g_topi[row] = make_int2(i0,i1);
    g_topw[row] = make_float2(w0, ee*w0);
    int p0 = atomicAdd(&g_cnt[i0],1);
    g_list[(size_t)i0*BN + p0] = row;
    int p1 = atomicAdd(&g_cnt[i1],1);
    g_list[(size_t)i1*BN + p1] = row;
  }
}

// ---------------- fused expert kernel ----------------
struct __align__(16) ExpSmem {
  float h1[64][258];            // layer-1 activations
  float h2[64][130];            // layer-2 activations
  union {
    struct { float A[64][20]; float B[16][256]; } g1;  // GEMM1 tiles
    float W2t[32][128];                                 // GEMM2 W tile
  } u;
};

__global__ void __launch_bounds__(256,1)
k_expert(){
  extern __shared__ char sraw[];
  ExpSmem& S = *reinterpret_cast<ExpSmem*>(sraw);
  __shared__ int rl[64];

  const int e = blockIdx.y;
  const int cnt = g_cnt[e];
  const int row0 = blockIdx.x*64;
  if (row0 >= cnt) return;

  const int t = threadIdx.x;
  const int tx = t & 15;
  const int ty = t >> 4;
  const int lane = t & 31;
  const int w = t >> 5;
  const int r0 = ty*4;

  if (t < 64){
    int i = row0 + t;
    rl[t] = g_list[(size_t)e*BN + (i < cnt ? i : row0)];
  }
  __syncthreads();

  // ---- GEMM1: [64 x 256] = xhat[rows,768] @ W1f[e] ----
  float2 acc[4][8];
#pragma unroll
  for (int i=0;i<4;i++)
#pragma unroll
    for (int j=0;j<8;j++) acc[i][j] = make_float2(0.f,0.f);

  for (int k0=0;k0<DD;k0+=16){
    {
      int r = t>>2, kc = (t&3)<<2;
      float4 vA = *(const float4*)(g_xhat + (size_t)rl[r]*DD + k0 + kc);
      *(float4*)&S.u.g1.A[r][kc] = vA;
    }
    const float* wsrc = g_W1f + ((size_t)e*DD + k0)*HD;
#pragma unroll
    for (int q=0;q<4;q++){
      int idx = q*1024 + t*4;
      int rr = idx>>8, cc = idx&255;
      *(float4*)&S.u.g1.B[rr][cc] = *(const float4*)(wsrc + rr*HD + cc);
    }
    __syncthreads();
#pragma unroll
    for (int kk=0;kk<16;kk++){
      float a0=S.u.g1.A[r0+0][kk], a1=S.u.g1.A[r0+1][kk];
      float a2=S.u.g1.A[r0+2][kk], a3=S.u.g1.A[r0+3][kk];
      float2 A0=make_float2(a0,a0), A1=make_float2(a1,a1);
      float2 A2=make_float2(a2,a2), A3=make_float2(a3,a3);
#pragma unroll
      for (int j=0;j<8;j++){
        float2 b = *(const float2*)&S.u.g1.B[kk][2*tx+32*j];
        ffma2(acc[0][j],A0,b); ffma2(acc[1][j],A1,b);
        ffma2(acc[2][j],A2,b); ffma2(acc[3][j],A3,b);
      }
    }
    __syncthreads();
  }

  // epilogue 1: bias + gelu -> h1
  {
    const float* c1 = g_c1f + e*HD;
#pragma unroll
    for (int i=0;i<4;i++)
#pragma unroll
      for (int j=0;j<8;j++){
        int c = 2*tx + 32*j;
        float2 v = acc[i][j];
        v.x = gelu_exact(v.x + c1[c]);
        v.y = gelu_exact(v.y + c1[c+1]);
        *(float2*)&S.h1[r0+i][c] = v;
      }
  }
  __syncthreads();

  // LN over h1 rows (256 cols): warp w handles rows 8w..8w+7
#pragma unroll
  for (int i=0;i<8;i++){
    int r = 8*w + i;
    float s=0.f, s2=0.f;
#pragma unroll
    for (int q=0;q<8;q++){ float v = S.h1[r][lane+32*q]; s+=v; s2+=v*v; }
    s = warpSum(s); s2 = warpSum(s2);
    float mu = s*(1.f/256.f);
    float rstd = rsqrtf(fmaxf(s2*(1.f/256.f)-mu*mu,0.f)+LNEPS);
#pragma unroll
    for (int q=0;q<8;q++){
      int c = lane+32*q;
      S.h1[r][c] = (S.h1[r][c]-mu)*rstd;
    }
  }
  __syncthreads();

  // ---- GEMM2: [64 x 128] = h1hat @ W2f[e] ----
  float2 acc2[4][4];
#pragma unroll
  for (int i=0;i<4;i++)
#pragma unroll
    for (int j=0;j<4;j++) acc2[i][j] = make_float2(0.f,0.f);

  for (int k0=0;k0<HD;k0+=32){
    const float* w2src = g_W2f + ((size_t)e*HD + k0)*H2;
#pragma unroll
    for (int q=0;q<4;q++){
      int idx = q*1024 + t*4;
      int rr = idx>>7, cc = idx&127;
      *(float4*)&S.u.W2t[rr][cc] = *(const float4*)(w2src + rr*H2 + cc);
    }
    __syncthreads();
#pragma unroll
    for (int kk=0;kk<32;kk++){
      float a0=S.h1[r0+0][k0+kk], a1=S.h1[r0+1][k0+kk];
      float a2=S.h1[r0+2][k0+kk], a3=S.h1[r0+3][k0+kk];
      float2 A0=make_float2(a0,a0), A1=make_float2(a1,a1);
      float2 A2=make_float2(a2,a2), A3=make_float2(a3,a3);
#pragma unroll
      for (int j=0;j<4;j++){
        float2 b = *(const float2*)&S.u.W2t[kk][2*tx+32*j];
        ffma2(acc2[0][j],A0,b); ffma2(acc2[1][j],A1,b);
        ffma2(acc2[2][j],A2,b); ffma2(acc2[3][j],A3,b);
      }
    }
    __syncthreads();
  }

  // epilogue 2: bias + gelu -> h2
  {
    const float* c2 = g_c2f + e*H2;
#pragma unroll
    for (int i=0;i<4;i++)
#pragma unroll
      for (int j=0;j<4;j++){
        int c = 2*tx + 32*j;
        float2 v = acc2[i][j];
        v.x = gelu_exact(v.x + c2[c]);
        v.y = gelu_exact(v.y + c2[c+1]);
        *(float2*)&S.h2[r0+i][c] = v;
      }
  }
  __syncthreads();

  // LN over h2 rows (128 cols)
#pragma unroll
  for (int i=0;i<8;i++){
    int r = 8*w + i;
    float s=0.f, s2=0.f;
#pragma unroll
    for (int q=0;q<4;q++){ float v = S.h2[r][lane+32*q]; s+=v; s2+=v*v; }
    s = warpSum(s); s2 = warpSum(s2);
    float mu = s*(1.f/128.f);
    float rstd = rsqrtf(fmaxf(s2*(1.f/128.f)-mu*mu,0.f)+LNEPS);
#pragma unroll
    for (int q=0;q<4;q++){
      int c = lane+32*q;
      S.h2[r][c] = (S.h2[r][c]-mu)*rstd;
    }
  }
  __syncthreads();

  // layer 3: dot with folded w3
  {
    const float* w3 = g_W3f + e*H2;
    const float c3 = g_c3f[e];
#pragma unroll
    for (int i=0;i<8;i++){
      int r = 8*w + i;
      float s = 0.f;
#pragma unroll
      for (int q=0;q<4;q++){
        int c = lane+32*q;
        s += S.h2[r][c]*w3[c];
      }
      s = warpSum(s);
      if (lane==0 && row0 + r < cnt)
        g_outs[(size_t)e*BN + rl[r]] = s + c3;
    }
  }
}

// ---------------- final combine ----------------
__global__ void k_final(float* __restrict__ out){
  int r = blockIdx.x*256 + threadIdx.x;
  int2 ti = g_topi[r];
  float2 tw = g_topw[r];
  out[OFF_FINAL + r] = tw.x*g_outs[(size_t)ti.x*BN + r]
                     + tw.y*g_outs[(size_t)ti.y*BN + r];
}

// ---------------- stats ----------------
__global__ void k_stats1(const float* __restrict__ lg){
  float p[8] = {0,0,0,0,0,0,0,0};
  for (int r = blockIdx.x*blockDim.x + threadIdx.x; r < BN; r += gridDim.x*blockDim.x){
    const float* L = lg + (size_t)r*8;
    float l[8], m = L[0];
#pragma unroll
    for (int e=0;e<8;e++){ l[e]=L[e]; m = fmaxf(m,l[e]); }
    float s = 0.f, ex[8];
#pragma unroll
    for (int e=0;e<8;e++){ ex[e]=expf(l[e]-m); s+=ex[e]; }
    float inv = 1.f/s;
#pragma unroll
    for (int e=0;e<8;e++) p[e] += ex[e]*inv;
  }
#pragma unroll
  for (int e=0;e<8;e++){
    float v = blockSumTo0(p[e]);
    if (threadIdx.x==0) g_part[blockIdx.x*8+e] = v;
  }
}

__global__ void k_stats2(float* __restrict__ out){
  int t = threadIdx.x;
  if (t < 8){
    float s = 0.f;
    for (int b=0;b<64;b++) s += g_part[b*8+t];
    out[OFF_PROB + t] = s*(1.f/(float)BN);
    out[OFF_FRAC + t] = (float)g_cnt[t]*(1.f/(float)BN);
  }
}

// ---------------- launch ----------------
extern "C" void kernel_launch(void* const* d_in, const int* in_sizes, int n_in,
                              void* d_out, int out_size) {
  const float* x    = (const float*)d_in[0];
  const float* g_in = (const float*)d_in[1];
  const float* b_in = (const float*)d_in[2];
  const float* g_r  = (const float*)d_in[3];
  const float* b_r  = (const float*)d_in[4];
  const float* Wr   = (const float*)d_in[5];
  const float* br   = (const float*)d_in[6];
  const float* ln1g = (const float*)d_in[7];
  const float* ln1b = (const float*)d_in[8];
  const float* W1   = (const float*)d_in[9];
  const float* b1   = (const float*)d_in[10];
  const float* ln2g = (const float*)d_in[11];
  const float* ln2b = (const float*)d_in[12];
  const float* W2   = (const float*)d_in[13];
  const float* b2   = (const float*)d_in[14];
  const float* ln3g = (const float*)d_in[15];
  const float* ln3b = (const float*)d_in[16];
  const float* W3   = (const float*)d_in[17];
  const float* b3   = (const float*)d_in[18];
  float* out = (float*)d_out;

  k_zero<<<1,32>>>();
  k_fold_router<<<EE,256>>>(g_r, b_r, Wr, br);
  k_fold_w1<<<(EE*DD*HD)/256,256>>>(ln1g, W1);
  k_fold_c1<<<dim3(HD,EE),256>>>(ln1b, W1, b1);
  k_fold_w2<<<(EE*HD*H2)/256,256>>>(ln2g, W2);
  k_fold_c2<<<dim3(H2,EE),256>>>(ln2b, W2, b2);
  k_fold_l3<<<EE,H2>>>(ln3g, ln3b, W3, b3);

  k_rows<<<BN/8,256>>>(x, g_in, b_in, out + OFF_LOG);

  int smem = (int)sizeof(ExpSmem);
  cudaFuncSetAttribute(k_expert, cudaFuncAttributeMaxDynamicSharedMemorySize, smem);
  k_expert<<<dim3(BN/64, EE),256,smem>>>();

  k_final<<<BN/256,256>>>(out);
  k_stats1<<<64,256>>>(out + OFF_LOG);
  k_stats2<<<1,32>>>(out);
}